// round 5
// baseline (speedup 1.0000x reference)
#include <cuda_runtime.h>

#define BLOCK 128
#define RPT 4      // rows per thread
#define BETA_C 0.99f
#define EPS_V 1e-3f
#define LOG_2PI_C 1.8378770664093453f

__device__ double g_accum = 0.0;
__device__ unsigned int g_count = 0;

static __device__ __forceinline__ unsigned long long pack2(float lo, float hi) {
    unsigned long long r;
    asm("mov.b64 %0, {%1, %2};" : "=l"(r) : "f"(lo), "f"(hi));
    return r;
}
static __device__ __forceinline__ void unpack2(unsigned long long v, float& lo, float& hi) {
    asm("mov.b64 {%0, %1}, %2;" : "=f"(lo), "=f"(hi) : "l"(v));
}
static __device__ __forceinline__ unsigned long long ffma2(unsigned long long a,
                                                           unsigned long long b,
                                                           unsigned long long c) {
    unsigned long long d;
    asm("fma.rn.f32x2 %0, %1, %2, %3;" : "=l"(d) : "l"(a), "l"(b), "l"(c));
    return d;
}
static __device__ __forceinline__ unsigned long long relu2(unsigned long long a) {
    float lo, hi;
    unpack2(a, lo, hi);
    lo = fmaxf(lo, 0.0f);
    hi = fmaxf(hi, 0.0f);
    return pack2(lo, hi);
}

// Per-row epilogue: Lyapunov scaling + rsample + NLL contribution.
static __device__ __forceinline__ float row_epilogue(
    float x0, float x1, float mu0, float mu1, float lv0, float lv1,
    float y0, float y1, float e0, float e1,
    float wv00, float wv01, float wv10, float wv11,
    float& fx0, float& fx1)
{
    float t0 = fmaf(x1, wv10, x0 * wv00);
    float t1 = fmaf(x1, wv11, x0 * wv01);
    float Vx = fmaf(t0, t0, fmaf(t1, t1, EPS_V));
    float m0 = fmaf(mu1, wv10, mu0 * wv00);
    float m1 = fmaf(mu1, wv11, mu0 * wv01);
    float Vmu = fmaf(m0, m0, fmaf(m1, m1, EPS_V));
    // a - relu(a-b) == min(a,b)
    float scale = __fdividef(fminf(BETA_C * Vx, Vmu), Vmu);
    float ms0 = mu0 * scale, ms1 = mu1 * scale;
    // sqrt(var) = exp(0.5*lv); 1/var = exp(-lv); log(var) = lv
    float s0 = __expf(0.5f * lv0), s1 = __expf(0.5f * lv1);
    fx0 = fmaf(s0, e0, ms0);
    fx1 = fmaf(s1, e1, ms1);
    float iv0 = __expf(-lv0), iv1 = __expf(-lv1);
    float d0 = y0 - ms0, d1 = y1 - ms1;
    return 0.5f * (fmaf(d0 * d0, iv0, d1 * d1 * iv1) + lv0 + lv1 + 2.0f * LOG_2PI_C);
}

__global__ void __launch_bounds__(BLOCK) mdn_main(
    const float* __restrict__ x, const float* __restrict__ y, const float* __restrict__ eps,
    const float* __restrict__ W1, const float* __restrict__ b1,
    const float* __restrict__ W2, const float* __restrict__ b2,
    const float* __restrict__ Wv, float* __restrict__ out_fx,
    int B, long out_last)
{
    // j-pair packed weights: sW[jp] = { {W1[0][2jp],W1[0][2jp+1]}, {W1[1][..] pair},
    //                                   {b1 pair}, {W2[.][0] pair},
    //                                   {W2[.][1] pair}, {W2[.][2] pair},
    //                                   {W2[.][3] pair}, pad }
    // All pairs are natural (j, j+1) packing -> no in-loop duplication MOVs.
    __shared__ ulonglong2 sW[32][4];

    int tid = threadIdx.x;
    if (tid < 32) {
        int j0 = 2 * tid;
        float4 wa = ((const float4*)W2)[j0];       // W2[j0][0..3]
        float4 wb = ((const float4*)W2)[j0 + 1];   // W2[j0+1][0..3]
        sW[tid][0] = make_ulonglong2(pack2(W1[j0], W1[j0 + 1]),
                                     pack2(W1[64 + j0], W1[64 + j0 + 1]));
        sW[tid][1] = make_ulonglong2(pack2(b1[j0], b1[j0 + 1]),
                                     pack2(wa.x, wb.x));
        sW[tid][2] = make_ulonglong2(pack2(wa.y, wb.y),
                                     pack2(wa.z, wb.z));
        sW[tid][3] = make_ulonglong2(pack2(wa.w, wb.w), 0ULL);
    }
    __syncthreads();

    long t = (long)blockIdx.x * BLOCK + tid;
    long row0 = t * RPT;
    float nll = 0.0f;

    if (row0 + RPT <= (long)B) {
        const float4* X4 = (const float4*)x + t * (RPT / 2);
        const float4* Y4 = (const float4*)y + t * (RPT / 2);
        const float4* E4 = (const float4*)eps + t * (RPT / 2);
        float4* O4 = (float4*)out_fx + t * (RPT / 2);

        // Per-row duplicated inputs (made once) and j-packed accumulators.
        unsigned long long x0d[RPT], x1d[RPT];
        unsigned long long a0[RPT], a1[RPT], a2[RPT], a3[RPT];

        #pragma unroll
        for (int k = 0; k < RPT / 2; k++) {
            float4 xv = X4[k];                 // rows 2k, 2k+1
            x0d[2 * k]     = pack2(xv.x, xv.x);
            x1d[2 * k]     = pack2(xv.y, xv.y);
            x0d[2 * k + 1] = pack2(xv.z, xv.z);
            x1d[2 * k + 1] = pack2(xv.w, xv.w);
        }
        #pragma unroll
        for (int r = 0; r < RPT; r++) {
            a0[r] = 0ULL; a1[r] = 0ULL; a2[r] = 0ULL; a3[r] = 0ULL;
        }

        #pragma unroll 2
        for (int jp = 0; jp < 32; jp++) {
            ulonglong2 q0 = sW[jp][0];
            ulonglong2 q1 = sW[jp][1];
            ulonglong2 q2 = sW[jp][2];
            ulonglong2 q3 = sW[jp][3];
            #pragma unroll
            for (int r = 0; r < RPT; r++) {
                unsigned long long h =
                    relu2(ffma2(x0d[r], q0.x, ffma2(x1d[r], q0.y, q1.x)));
                a0[r] = ffma2(h, q1.y, a0[r]);
                a1[r] = ffma2(h, q2.x, a1[r]);
                a2[r] = ffma2(h, q2.y, a2[r]);
                a3[r] = ffma2(h, q3.x, a3[r]);
            }
        }

        // Scalars after the mainloop to keep its live set small.
        float wv00 = __ldg(Wv + 0), wv01 = __ldg(Wv + 1);
        float wv10 = __ldg(Wv + 2), wv11 = __ldg(Wv + 3);
        float c0 = __ldg(b2 + 0), c1 = __ldg(b2 + 1), c2 = __ldg(b2 + 2), c3 = __ldg(b2 + 3);

        float fx[2 * RPT];
        #pragma unroll
        for (int r = 0; r < RPT; r++) {
            float lo, hi, x0v, x1v, dmy;
            unpack2(a0[r], lo, hi); float mu0 = lo + hi + c0;
            unpack2(a1[r], lo, hi); float mu1 = lo + hi + c1;
            unpack2(a2[r], lo, hi); float lv0 = lo + hi + c2;
            unpack2(a3[r], lo, hi); float lv1 = lo + hi + c3;
            unpack2(x0d[r], x0v, dmy);
            unpack2(x1d[r], x1v, dmy);
            int k = r / 2, half = r & 1;
            float4 yv = Y4[k];
            float4 ev = E4[k];
            float y0v = half ? yv.z : yv.x, y1v = half ? yv.w : yv.y;
            float e0v = half ? ev.z : ev.x, e1v = half ? ev.w : ev.y;
            nll += row_epilogue(x0v, x1v, mu0, mu1, lv0, lv1,
                                y0v, y1v, e0v, e1v,
                                wv00, wv01, wv10, wv11, fx[2 * r], fx[2 * r + 1]);
        }
        #pragma unroll
        for (int k = 0; k < RPT / 2; k++)
            O4[k] = make_float4(fx[4 * k], fx[4 * k + 1], fx[4 * k + 2], fx[4 * k + 3]);
    } else if (row0 < (long)B) {
        // Tail fallback.
        float wv00 = __ldg(Wv + 0), wv01 = __ldg(Wv + 1);
        float wv10 = __ldg(Wv + 2), wv11 = __ldg(Wv + 3);
        float c0 = __ldg(b2 + 0), c1 = __ldg(b2 + 1), c2 = __ldg(b2 + 2), c3 = __ldg(b2 + 3);
        for (long r = row0; r < (long)B; r++) {
            float x0 = x[2 * r], x1 = x[2 * r + 1];
            float f0 = c0, f1 = c1, f2 = c2, f3 = c3;
            for (int jp = 0; jp < 32; jp++) {
                ulonglong2 q0 = sW[jp][0];
                ulonglong2 q1 = sW[jp][1];
                ulonglong2 q2 = sW[jp][2];
                ulonglong2 q3 = sW[jp][3];
                float wa0, wa1, wb0, wb1, bb0, bb1;
                unpack2(q0.x, wa0, wa1);
                unpack2(q0.y, wb0, wb1);
                unpack2(q1.x, bb0, bb1);
                float h0 = fmaxf(fmaf(x0, wa0, fmaf(x1, wb0, bb0)), 0.0f);
                float h1 = fmaxf(fmaf(x0, wa1, fmaf(x1, wb1, bb1)), 0.0f);
                float w0a, w0b, w1a, w1b, w2a, w2b, w3a, w3b;
                unpack2(q1.y, w0a, w0b);
                unpack2(q2.x, w1a, w1b);
                unpack2(q2.y, w2a, w2b);
                unpack2(q3.x, w3a, w3b);
                f0 = fmaf(h0, w0a, fmaf(h1, w0b, f0));
                f1 = fmaf(h0, w1a, fmaf(h1, w1b, f1));
                f2 = fmaf(h0, w2a, fmaf(h1, w2b, f2));
                f3 = fmaf(h0, w3a, fmaf(h1, w3b, f3));
            }
            float fx0, fx1;
            nll += row_epilogue(x0, x1, f0, f1, f2, f3,
                                y[2 * r], y[2 * r + 1],
                                eps[2 * r], eps[2 * r + 1],
                                wv00, wv01, wv10, wv11, fx0, fx1);
            out_fx[2 * r] = fx0;
            out_fx[2 * r + 1] = fx1;
        }
    }

    // Block reduction of nll (float) -> one double atomic per block.
    unsigned mask = 0xFFFFFFFFu;
    #pragma unroll
    for (int off = 16; off > 0; off >>= 1)
        nll += __shfl_down_sync(mask, nll, off);
    __shared__ float red[BLOCK / 32];
    __shared__ bool s_is_last;
    int wid = tid >> 5, lid = tid & 31;
    if (lid == 0) red[wid] = nll;
    __syncthreads();
    if (wid == 0) {
        float v = (lid < BLOCK / 32) ? red[lid] : 0.0f;
        #pragma unroll
        for (int off = 2; off > 0; off >>= 1)
            v += __shfl_down_sync(mask, v, off);
        if (lid == 0) {
            atomicAdd(&g_accum, (double)v);
            __threadfence();
            unsigned int done = atomicAdd(&g_count, 1u);
            s_is_last = (done == gridDim.x - 1);
        }
    }
    __syncthreads();
    // Last block to finish: publish the scalar and reset globals for next replay.
    if (s_is_last && tid == 0) {
        double total = *((volatile double*)&g_accum);
        out_fx[out_last] = (float)total;
        *((volatile double*)&g_accum) = 0.0;
        __threadfence();
        *((volatile unsigned int*)&g_count) = 0u;
    }
}

extern "C" void kernel_launch(void* const* d_in, const int* in_sizes, int n_in,
                              void* d_out, int out_size) {
    const float* x   = (const float*)d_in[0];
    const float* y   = (const float*)d_in[1];
    const float* eps = (const float*)d_in[2];
    const float* W1  = (const float*)d_in[3];
    const float* b1  = (const float*)d_in[4];
    const float* W2  = (const float*)d_in[5];
    const float* b2  = (const float*)d_in[6];
    const float* Wv  = (const float*)d_in[7];
    float* out = (float*)d_out;

    int B = in_sizes[0] / 2;
    long nthreads = ((long)B + RPT - 1) / RPT;
    int blocks = (int)((nthreads + BLOCK - 1) / BLOCK);

    mdn_main<<<blocks, BLOCK>>>(x, y, eps, W1, b1, W2, b2, Wv, out,
                                B, (long)out_size - 1);
}